// round 13
// baseline (speedup 1.0000x reference)
#include <cuda_runtime.h>
#include <cuda_fp16.h>
#include <cstdint>
#include <math.h>

#define N_ROWS 65536
#define DIM    512
#define KCODES 1024

#define QUANT_OFF 1
#define PERP_OFF  (1 + N_ROWS * DIM)
#define ENC_OFF   (2 + (size_t)N_ROWS * DIM)

// pass1: CTA = 64 rows x 1024 codes (8 nc x 8 kc chunks), 2 CTAs/SM
#define BM 64
#define BN 128
#define KC 64
#define MARGIN 0.03125f
#define CAND_CAP 32
#define WSCALE_INV (2.0f / 1024.0f)     // undo w*1024, apply the -2 factor

// pass1 smem byte offsets (per CTA)
#define SM_A    0              // A resident: [64 rows][512 k] half = 65536
#define SM_B    65536          // 2 x [128 codes][64 k] half (xor-swizzled) = 2x16384
#define SM_BBUF 16384
#define SM_WN   98304          // 128 f32
#define SM_XN   98816          // 64 f32
#define SM_MIN  99072          // 64 u64
#define SM_CNT  99584          // 64 int
#define SM_CAND 99840          // 64 x 32 u16 = 4096
#define SM_TOT  103936         // x2 CTAs = 207872 <= 227KB limit

// ---- scratch ----
__device__ __align__(16) __half2 g_xh2[(size_t)N_ROWS * 256];   // fp16 X (32MB)
__device__ __align__(16) __half2 g_wh2[KCODES * 256];           // fp16 W*1024 (1MB)
__device__ float  g_wnorm[KCODES];
__device__ float  g_xnorm[N_ROWS];
__device__ int    g_idx[N_ROWS];
__device__ int    g_counts[KCODES];
__device__ unsigned short g_cand[(size_t)N_ROWS * CAND_CAP];
__device__ int    g_ccount[N_ROWS];
__device__ double g_sse;

// ---- helpers ----
static __device__ __forceinline__ uint64_t cvta_g(const void* p) {
    uint64_t a; asm("cvta.to.global.u64 %0, %1;" : "=l"(a) : "l"(p)); return a;
}
static __device__ __forceinline__ uint32_t smem_u32(const void* p) {
    uint32_t a;
    asm("{ .reg .u64 t; cvta.to.shared.u64 t, %1; cvt.u32.u64 %0, t; }" : "=r"(a) : "l"(p));
    return a;
}
static __device__ __forceinline__ void cp16(uint32_t s, uint64_t g) {
    asm volatile("cp.async.cg.shared.global [%0], [%1], 16;" :: "r"(s), "l"(g));
}
#define CP_COMMIT() asm volatile("cp.async.commit_group;")
#define CP_WAIT(n)  asm volatile("cp.async.wait_group %0;" :: "n"(n))

// ============================================================
// prep W: wnorm + fp16 copy (x1024) + zero counts/sse
// ============================================================
__global__ void vq_wprep(const float* __restrict__ W) {
    int w = threadIdx.x >> 5, lane = threadIdx.x & 31;
    int code = blockIdx.x * 8 + w;
    const float2* row = (const float2*)(W + (size_t)code * DIM);
    float s = 0.f;
#pragma unroll
    for (int t = 0; t < 8; t++) {
        float2 v = row[lane + t * 32];
        s += v.x * v.x + v.y * v.y;
        g_wh2[code * 256 + lane + t * 32] =
            __floats2half2_rn(v.x * 1024.f, v.y * 1024.f);
    }
#pragma unroll
    for (int o = 16; o > 0; o >>= 1) s += __shfl_down_sync(0xffffffffu, s, o);
    if (lane == 0) g_wnorm[code] = s;
    if (blockIdx.x == 0) {
        for (int i = threadIdx.x; i < KCODES; i += blockDim.x) g_counts[i] = 0;
        if (threadIdx.x == 0) g_sse = 0.0;
    }
}

// prep X: xnorm + fp16 copy
__global__ void vq_xprep(const float* __restrict__ X) {
    int w = threadIdx.x >> 5, lane = threadIdx.x & 31;
    int r = blockIdx.x * 8 + w;
    const float2* row = (const float2*)(X + (size_t)r * DIM);
    float s = 0.f;
#pragma unroll
    for (int t = 0; t < 8; t++) {
        float2 v = row[lane + t * 32];
        s += v.x * v.x + v.y * v.y;
        g_xh2[(size_t)r * 256 + lane + t * 32] = __floats2half2_rn(v.x, v.y);
    }
#pragma unroll
    for (int o = 16; o > 0; o >>= 1) s += __shfl_down_sync(0xffffffffu, s, o);
    if (lane == 0) g_xnorm[r] = s;
}

// ============================================================
// B chunk staging: [128 codes][64 k] half, 16B-granule xor swizzle
// ============================================================
static __device__ __forceinline__ void stage_b(
    uint32_t sb, int c0, int kc, int buf, int tid)
{
    uint64_t wsrc = cvta_g(g_wh2) + (size_t)c0 * 1024 + kc * 128;
    uint32_t dst = sb + SM_B + buf * SM_BBUF;
#pragma unroll
    for (int i = 0; i < 4; i++) {
        int f = tid + i * 256;          // 0..1023 granules
        int code = f >> 3, g = f & 7;
        cp16(dst + (code * 8 + (g ^ (code & 7))) * 16,
             wsrc + (size_t)code * 1024 + g * 16);
    }
}

// ============================================================
// pass 1: fp16 HFMA2 GEMM + candidate collection
// 256 thr = 8(tr) x 32(tc); thread = 8 rows x 4 codes (cols j*32+tc)
// ============================================================
__global__ void __launch_bounds__(256, 2)
vq_pass1(void) {
    extern __shared__ __align__(16) char smem[];
    const uint32_t sb = smem_u32(smem);
    float* sWn = (float*)(smem + SM_WN);
    float* sXn = (float*)(smem + SM_XN);
    unsigned long long* sMin = (unsigned long long*)(smem + SM_MIN);
    int* sCnt = (int*)(smem + SM_CNT);
    unsigned short* sCand = (unsigned short*)(smem + SM_CAND);

    const int tid = threadIdx.x;
    const int tr = tid >> 5, tc = tid & 31;
    const int r0 = blockIdx.x * BM;

    // prologue: A resident (64 rows x 1024B) + B chunk0
    {
        uint64_t xsrc = cvta_g(g_xh2) + (size_t)r0 * 1024;
#pragma unroll
        for (int i = 0; i < 16; i++) {
            int f = tid + i * 256;          // 0..4095 granules
            cp16(sb + SM_A + f * 16, xsrc + (size_t)f * 16);
        }
    }
    stage_b(sb, 0, 0, 0, tid);
    CP_COMMIT();

    if (tid < BM) {
        sXn[tid] = g_xnorm[r0 + tid];
        sMin[tid] = 0xFFFFFFFFFFFFFFFFull;
        sCnt[tid] = 0;
    }

    __half2 acc[8][4];

    for (int t = 0; t < 64; t++) {
        const int nc = t >> 3, kc = t & 7, buf = t & 1;
        __syncthreads();                 // readers of buf (t-2) done
        if (t + 1 < 64) {
            const int nt = t + 1;
            stage_b(sb, (nt >> 3) * BN, nt & 7, buf ^ 1, tid);
            CP_COMMIT();
            CP_WAIT(1);                  // chunk t (and A) landed
        } else {
            CP_WAIT(0);
        }
        __syncthreads();

        if (kc == 0) {
            if (tid < BN) sWn[tid] = g_wnorm[nc * BN + tid];
            const __half2 z = __floats2half2_rn(0.f, 0.f);
#pragma unroll
            for (int i = 0; i < 8; i++)
#pragma unroll
                for (int j = 0; j < 4; j++) acc[i][j] = z;
        }

        const char* pB = smem + SM_B + buf * SM_BBUF;
        const char* pA = smem + SM_A + kc * 128;
        const int swz = tc & 7;          // (j*32+tc)&7 == tc&7
#pragma unroll
        for (int k8 = 0; k8 < 8; k8++) {
            const int g = (k8 ^ swz) * 16;
            uint4 bvr[4];
#pragma unroll
            for (int j = 0; j < 4; j++)
                bvr[j] = *(const uint4*)(pB + (j * 32 + tc) * 128 + g);
#pragma unroll
            for (int i = 0; i < 8; i++) {
                uint4 avr = *(const uint4*)(pA + (tr * 8 + i) * 1024 + k8 * 16);
                const __half2* ah = (const __half2*)&avr;
#pragma unroll
                for (int j = 0; j < 4; j++) {
                    const __half2* bh = (const __half2*)&bvr[j];
                    acc[i][j] = __hfma2(ah[0], bh[0], acc[i][j]);
                    acc[i][j] = __hfma2(ah[1], bh[1], acc[i][j]);
                    acc[i][j] = __hfma2(ah[2], bh[2], acc[i][j]);
                    acc[i][j] = __hfma2(ah[3], bh[3], acc[i][j]);
                }
            }
        }

        if (kc == 7) {
            // ---- epilogue: approx distances; min merge then collect ----
            const int c0 = nc * BN;
#pragma unroll
            for (int i = 0; i < 8; i++) {
                int row = tr * 8 + i;
                float xn = sXn[row];
                unsigned long long pk = 0xFFFFFFFFFFFFFFFFull;
#pragma unroll
                for (int j = 0; j < 4; j++) {
                    int col = j * 32 + tc;
                    float2 f2 = __half22float2(acc[i][j]);
                    float d = (xn + sWn[col]) - (f2.x + f2.y) * WSCALE_INV;
                    unsigned long long p =
                        ((unsigned long long)__float_as_uint(d) << 32)
                        | (unsigned)(c0 + col);
                    if (p < pk) pk = p;
                }
                atomicMin(&sMin[row], pk);
            }
            __syncthreads();
#pragma unroll
            for (int i = 0; i < 8; i++) {
                int row = tr * 8 + i;
                float xn = sXn[row];
                float thr = __uint_as_float((unsigned)(sMin[row] >> 32)) + MARGIN;
#pragma unroll
                for (int j = 0; j < 4; j++) {
                    int col = j * 32 + tc;
                    float2 f2 = __half22float2(acc[i][j]);
                    float d = (xn + sWn[col]) - (f2.x + f2.y) * WSCALE_INV;
                    if (d <= thr) {
                        int pos = atomicAdd(&sCnt[row], 1);
                        if (pos < CAND_CAP)
                            sCand[row * CAND_CAP + pos] =
                                (unsigned short)(c0 + col);
                    }
                }
            }
        }
    }

    __syncthreads();
    if (tid < BM) {
        int r = r0 + tid;
        int cnt = sCnt[tid];
        g_ccount[r] = cnt;
        int m = cnt < CAND_CAP ? cnt : CAND_CAP;
        for (int i = 0; i < m; i++)
            g_cand[(size_t)r * CAND_CAP + i] = sCand[tid * CAND_CAP + i];
    }
}

// ============================================================
// pass 2: exact fp32 verify of candidates; first-index tie-break
// ============================================================
__global__ void __launch_bounds__(256)
vq_pass2(const float* __restrict__ X, const float* __restrict__ W) {
    const int w = threadIdx.x >> 5, lane = threadIdx.x & 31;
    const int r = blockIdx.x * 8 + w;
    const float* xr = X + (size_t)r * DIM;
    float xv[16];
#pragma unroll
    for (int i = 0; i < 16; i++) xv[i] = xr[lane + 32 * i];
    const float xn = g_xnorm[r];
    const int cnt = g_ccount[r];
    unsigned long long best = 0xFFFFFFFFFFFFFFFFull;

    if (cnt <= CAND_CAP) {
        for (int c = 0; c < cnt; c++) {
            int idx = g_cand[(size_t)r * CAND_CAP + c];
            const float* wr = W + (size_t)idx * DIM;
            float s = 0.f;
#pragma unroll
            for (int i = 0; i < 16; i++) s += xv[i] * wr[lane + 32 * i];
#pragma unroll
            for (int o = 16; o > 0; o >>= 1) s += __shfl_xor_sync(0xffffffffu, s, o);
            float d = (xn + g_wnorm[idx]) - 2.0f * s;
            unsigned long long p =
                ((unsigned long long)__float_as_uint(d) << 32) | (unsigned)idx;
            if (p < best) best = p;
        }
    } else {                              // overflow: exact scan of all codes
        for (int idx = 0; idx < KCODES; idx++) {
            const float* wr = W + (size_t)idx * DIM;
            float s = 0.f;
#pragma unroll
            for (int i = 0; i < 16; i++) s += xv[i] * wr[lane + 32 * i];
#pragma unroll
            for (int o = 16; o > 0; o >>= 1) s += __shfl_xor_sync(0xffffffffu, s, o);
            float d = (xn + g_wnorm[idx]) - 2.0f * s;
            unsigned long long p =
                ((unsigned long long)__float_as_uint(d) << 32) | (unsigned)idx;
            if (p < best) best = p;
        }
    }
    if (lane == 0) {
        int idx = (int)(best & 0xFFFFFFFFu);
        g_idx[r] = idx;
        atomicAdd(&g_counts[idx], 1);
    }
}

// ============================================================
// output: quantized_st + encodings + SSE
// outq is out+1 (4B-aligned) -> scalar stores; oute 8B-aligned -> float2.
// ============================================================
__global__ void __launch_bounds__(256)
vq_output_kernel(const float* __restrict__ X, const float* __restrict__ W,
                 float* __restrict__ outq, float* __restrict__ oute) {
    const int tid = threadIdx.x;
    const int r0  = blockIdx.x * 64;
    const int sub = tid >> 7, c4 = tid & 127;
    double lsum = 0.0;
#pragma unroll 4
    for (int i = 0; i < 32; i++) {
        int r = r0 + i * 2 + sub;
        int idx = g_idx[r];
        float4 xv = ((const float4*)(X + (size_t)r * DIM))[c4];
        float4 qv = ((const float4*)(W + (size_t)idx * DIM))[c4];
        float dx = qv.x - xv.x, dy = qv.y - xv.y, dz = qv.z - xv.z, dw = qv.w - xv.w;
        float* op = outq + (size_t)r * DIM + c4 * 4;
        op[0] = xv.x + dx; op[1] = xv.y + dy;
        op[2] = xv.z + dz; op[3] = xv.w + dw;
        lsum += (double)dx * dx + (double)dy * dy + (double)dz * dz + (double)dw * dw;
    }
    float2 z2 = make_float2(0.f, 0.f);
    for (int f = tid; f < 64 * (KCODES / 2); f += 256) {
        int row = f >> 9, q = f & 511;
        ((float2*)(oute + (size_t)(r0 + row) * KCODES))[q] = z2;
    }
    __syncthreads();
    if (tid < 64) {
        int r = r0 + tid;
        oute[(size_t)r * KCODES + g_idx[r]] = 1.0f;
    }
#pragma unroll
    for (int o = 16; o > 0; o >>= 1) lsum += __shfl_down_sync(0xffffffffu, lsum, o);
    __shared__ double sd[8];
    if ((tid & 31) == 0) sd[tid >> 5] = lsum;
    __syncthreads();
    if (tid == 0) {
        double s = 0.0;
        for (int v = 0; v < 8; v++) s += sd[v];
        atomicAdd(&g_sse, s);
    }
}

// ============================================================
__global__ void vq_finalize_kernel(float* __restrict__ out) {
    __shared__ float red[32];
    int tid = threadIdx.x;
    float p = (float)g_counts[tid] / 65536.0f;
    float t = p * logf(p + 1e-10f);
#pragma unroll
    for (int o = 16; o > 0; o >>= 1) t += __shfl_down_sync(0xffffffffu, t, o);
    if ((tid & 31) == 0) red[tid >> 5] = t;
    __syncthreads();
    if (tid < 32) {
        float v = red[tid];
#pragma unroll
        for (int o = 16; o > 0; o >>= 1) v += __shfl_down_sync(0xffffffffu, v, o);
        if (tid == 0) {
            out[PERP_OFF] = expf(-v);
            float m = (float)(g_sse / 33554432.0);
            out[0] = m + 0.25f * m;
        }
    }
}

// ============================================================
extern "C" void kernel_launch(void* const* d_in, const int* in_sizes, int n_in,
                              void* d_out, int out_size) {
    const float* X = (const float*)d_in[0];
    const float* W = (const float*)d_in[1];
    if (n_in >= 2 && in_sizes[0] == KCODES * DIM && in_sizes[1] == N_ROWS * DIM) {
        const float* t = X; X = W; W = t;
    }
    float* out  = (float*)d_out;
    float* outq = out + QUANT_OFF;
    float* oute = out + ENC_OFF;

    cudaFuncSetAttribute(vq_pass1,
                         cudaFuncAttributeMaxDynamicSharedMemorySize, SM_TOT);

    vq_wprep<<<128, 256>>>(W);
    vq_xprep<<<N_ROWS / 8, 256>>>(X);
    vq_pass1<<<N_ROWS / BM, 256, SM_TOT>>>();
    vq_pass2<<<N_ROWS / 8, 256>>>(X, W);
    vq_output_kernel<<<1024, 256>>>(X, W, outq, oute);
    vq_finalize_kernel<<<1, 1024>>>(out);
}

// round 14
// speedup vs baseline: 4.3055x; 4.3055x over previous
#include <cuda_runtime.h>
#include <cstdint>
#include <math.h>

#define N_ROWS 65536
#define DIM    512
#define KCODES 1024

#define QUANT_OFF 1
#define PERP_OFF  (1 + N_ROWS * DIM)
#define ENC_OFF   (2 + (size_t)N_ROWS * DIM)

// CTA = 64 rows x 1024 codes (8 nc x 8 kc chunks); 2 CTAs/SM
#define BM 64
#define BN 128
#define KC 64                  // k per chunk

// smem byte offsets (per CTA)
#define SM_A    0              // 2 x [64 rows][64 k] f32 = 2 x 16384
#define SM_ABUF 16384
#define SM_B    32768          // 2 x [128 codes][64 k] f32 (xor-swizzled) = 2 x 32768
#define SM_BBUF 32768
#define SM_WN   98304          // 128 f32
#define SM_XN   98816          // 64 f32
#define SM_BEST 99072          // 64 u64
#define SM_TOT  99584

// ---- scratch ----
__device__ float  g_wnorm[KCODES];
__device__ float  g_xnorm[N_ROWS];
__device__ int    g_idx[N_ROWS];
__device__ int    g_counts[KCODES];
__device__ double g_sse;

// ---- helpers ----
static __device__ __forceinline__ uint64_t cvta_g(const void* p) {
    uint64_t a; asm("cvta.to.global.u64 %0, %1;" : "=l"(a) : "l"(p)); return a;
}
static __device__ __forceinline__ uint32_t smem_u32(const void* p) {
    uint32_t a;
    asm("{ .reg .u64 t; cvta.to.shared.u64 t, %1; cvt.u32.u64 %0, t; }" : "=r"(a) : "l"(p));
    return a;
}
static __device__ __forceinline__ void cp16(uint32_t s, uint64_t g) {
    asm volatile("cp.async.cg.shared.global [%0], [%1], 16;" :: "r"(s), "l"(g));
}
#define CP_COMMIT() asm volatile("cp.async.commit_group;")
#define CP_WAIT(n)  asm volatile("cp.async.wait_group %0;" :: "n"(n))

// packed fp32x2 FMA: lanes accumulate independent (even-k, odd-k) partial dots
static __device__ __forceinline__ void fma2(unsigned long long& c,
                                            unsigned long long a,
                                            unsigned long long b) {
    asm("fma.rn.f32x2 %0, %1, %2, %0;" : "+l"(c) : "l"(a), "l"(b));
}
static __device__ __forceinline__ float unpack_sum(unsigned long long v) {
    float lo, hi;
    asm("mov.b64 {%0,%1}, %2;" : "=f"(lo), "=f"(hi) : "l"(v));
    return lo + hi;
}

// ============================================================
// merged prep: blocks [0,128) -> wnorm (+zero counts/sse),
//              blocks [128,8320) -> xnorm
// ============================================================
__global__ void vq_prep_all(const float* __restrict__ X,
                            const float* __restrict__ W) {
    const int b = blockIdx.x;
    const int w = threadIdx.x >> 5, lane = threadIdx.x & 31;
    if (b < 128) {
        int code = b * 8 + w;
        const float* row = W + (size_t)code * DIM;
        float s = 0.f;
#pragma unroll
        for (int t = 0; t < DIM / 32; t++) { float v = row[lane + t * 32]; s += v * v; }
#pragma unroll
        for (int o = 16; o > 0; o >>= 1) s += __shfl_down_sync(0xffffffffu, s, o);
        if (lane == 0) g_wnorm[code] = s;
        if (b == 0) {
            for (int i = threadIdx.x; i < KCODES; i += blockDim.x) g_counts[i] = 0;
            if (threadIdx.x == 0) g_sse = 0.0;
        }
    } else {
        int r = (b - 128) * 8 + w;
        const float* row = X + (size_t)r * DIM;
        float s = 0.f;
#pragma unroll
        for (int t = 0; t < DIM / 32; t++) { float v = row[lane + t * 32]; s += v * v; }
#pragma unroll
        for (int o = 16; o > 0; o >>= 1) s += __shfl_down_sync(0xffffffffu, s, o);
        if (lane == 0) g_xnorm[r] = s;
    }
}

// ============================================================
// chunk staging
// ============================================================
static __device__ __forceinline__ void stage_a(
    uint32_t sb, const float* __restrict__ X, int r0, int kc, int buf, int tid)
{
    uint64_t xsrc = cvta_g(X) + (size_t)r0 * (DIM * 4) + kc * (KC * 4);
    uint32_t dst = sb + SM_A + buf * SM_ABUF;
#pragma unroll
    for (int i = 0; i < 4; i++) {
        int f = tid + i * 256;          // 0..1023
        int row = f >> 4, k4 = f & 15;
        cp16(dst + row * 256 + k4 * 16,
             xsrc + (size_t)row * (DIM * 4) + k4 * 16);
    }
}
static __device__ __forceinline__ void stage_b(
    uint32_t sb, const float* __restrict__ W, int c0, int kc, int buf, int tid)
{
    uint64_t wsrc = cvta_g(W) + (size_t)c0 * (DIM * 4) + kc * (KC * 4);
    uint32_t dst = sb + SM_B + buf * SM_BBUF;
#pragma unroll
    for (int i = 0; i < 8; i++) {
        int f = tid + i * 256;          // 0..2047
        int code = f >> 4, k4 = f & 15;
        int col = k4 ^ (code & 15);
        cp16(dst + code * 256 + col * 16,
             wsrc + (size_t)code * (DIM * 4) + k4 * 16);
    }
}

// ============================================================
// main: f32x2 exact GEMM + fused argmin  (UNCHANGED from R12)
// 256 thr = 8(tr) x 32(tc); thread = 8 rows x 4 codes (cols j*32+tc)
// ============================================================
__global__ void __launch_bounds__(256, 2)
vq_main(const float* __restrict__ X, const float* __restrict__ W) {
    extern __shared__ __align__(16) char smem[];
    const uint32_t sb = smem_u32(smem);
    float* sWn = (float*)(smem + SM_WN);
    float* sXn = (float*)(smem + SM_XN);
    unsigned long long* sBest = (unsigned long long*)(smem + SM_BEST);

    const int tid = threadIdx.x;
    const int tr = tid >> 5, tc = tid & 31;
    const int r0 = blockIdx.x * BM;

    // prologue: chunk 0 (A kc=0, B nc=0/kc=0) into buf0
    stage_a(sb, X, r0, 0, 0, tid);
    stage_b(sb, W, 0, 0, 0, tid);
    CP_COMMIT();

    if (tid < BM) {
        sBest[tid] = 0xFFFFFFFFFFFFFFFFull;
        sXn[tid] = g_xnorm[r0 + tid];
    }

    unsigned long long acc[8][4];

    for (int t = 0; t < 64; t++) {
        const int nc = t >> 3, kc = t & 7, buf = t & 1;
        __syncthreads();                 // all warps done reading buf^1 (t-1)
        if (t + 1 < 64) {
            const int nt = t + 1;
            stage_a(sb, X, r0, nt & 7, buf ^ 1, tid);
            stage_b(sb, W, (nt >> 3) * BN, nt & 7, buf ^ 1, tid);
            CP_COMMIT();
            CP_WAIT(1);                  // chunk t landed
        } else {
            CP_WAIT(0);
        }
        __syncthreads();

        if (kc == 0) {
            if (tid < BN) sWn[tid] = g_wnorm[nc * BN + tid];
#pragma unroll
            for (int i = 0; i < 8; i++)
#pragma unroll
                for (int j = 0; j < 4; j++) acc[i][j] = 0ull;
        }

        const char* pB = smem + SM_B + buf * SM_BBUF;
        const float* pA = (const float*)(smem + SM_A + buf * SM_ABUF)
                          + (tr * 8) * KC;
#pragma unroll
        for (int k4 = 0; k4 < 16; k4++) {
            const int col16 = (k4 ^ (tc & 15)) << 4;
            ulonglong2 bv[4];
#pragma unroll
            for (int j = 0; j < 4; j++)
                bv[j] = *(const ulonglong2*)(pB + (j * 32 + tc) * 256 + col16);
#pragma unroll
            for (int i = 0; i < 8; i++) {
                ulonglong2 av = *(const ulonglong2*)(pA + i * KC + k4 * 4);
#pragma unroll
                for (int j = 0; j < 4; j++)
                    fma2(acc[i][j], av.x, bv[j].x);
#pragma unroll
                for (int j = 0; j < 4; j++)
                    fma2(acc[i][j], av.y, bv[j].y);
            }
        }

        if (kc == 7) {
            // ---- epilogue: distances + per-row argmin (first-index ties) ----
            const int c0 = nc * BN;
#pragma unroll
            for (int i = 0; i < 8; i++) {
                int row = tr * 8 + i;
                float xn = sXn[row];
                unsigned long long best = 0xFFFFFFFFFFFFFFFFull;
#pragma unroll
                for (int j = 0; j < 4; j++) {
                    int col = j * 32 + tc;
                    float dot = unpack_sum(acc[i][j]);
                    float d = (xn + sWn[col]) - 2.0f * dot;   // reference formula
                    unsigned key = __float_as_uint(d);
                    key = (key & 0x80000000u) ? ~key : (key | 0x80000000u);
                    unsigned long long pk =
                        ((unsigned long long)key << 32) | (unsigned)(c0 + col);
                    if (pk < best) best = pk;
                }
                atomicMin(&sBest[row], best);
            }
        }
    }

    __syncthreads();
    if (tid < BM) {
        int idx = (int)(sBest[tid] & 0xFFFFFFFFu);
        g_idx[r0 + tid] = idx;
        atomicAdd(&g_counts[idx], 1);
    }
}

// ============================================================
// output: quantized_st + encodings + SSE
// outq is out+1 (4B-aligned) -> scalar stores; oute 8B-aligned -> float2.
// fp32 independent accumulators (no DFMA chain); g_idx preloaded to smem.
// ============================================================
__global__ void __launch_bounds__(256)
vq_output_kernel(const float* __restrict__ X, const float* __restrict__ W,
                 float* __restrict__ outq, float* __restrict__ oute) {
    __shared__ int sIdx[64];
    const int tid = threadIdx.x;
    const int r0  = blockIdx.x * 64;
    const int sub = tid >> 7, c4 = tid & 127;
    if (tid < 64) sIdx[tid] = g_idx[r0 + tid];
    __syncthreads();

    float a0 = 0.f, a1 = 0.f, a2 = 0.f, a3 = 0.f;   // independent fp32 chains
#pragma unroll 4
    for (int i = 0; i < 32; i++) {
        int rl = i * 2 + sub;
        int r = r0 + rl;
        int idx = sIdx[rl];
        float4 xv = ((const float4*)(X + (size_t)r * DIM))[c4];
        float4 qv = ((const float4*)(W + (size_t)idx * DIM))[c4];
        float dx = qv.x - xv.x, dy = qv.y - xv.y, dz = qv.z - xv.z, dw = qv.w - xv.w;
        float* op = outq + (size_t)r * DIM + c4 * 4;
        op[0] = xv.x + dx; op[1] = xv.y + dy;
        op[2] = xv.z + dz; op[3] = xv.w + dw;
        a0 += dx * dx; a1 += dy * dy; a2 += dz * dz; a3 += dw * dw;
    }
    double lsum = (double)((a0 + a1) + (a2 + a3));

    float2 z2 = make_float2(0.f, 0.f);
    for (int f = tid; f < 64 * (KCODES / 2); f += 256) {
        int row = f >> 9, q = f & 511;
        ((float2*)(oute + (size_t)(r0 + row) * KCODES))[q] = z2;
    }
    __syncthreads();
    if (tid < 64) {
        int r = r0 + tid;
        oute[(size_t)r * KCODES + sIdx[tid]] = 1.0f;
    }
#pragma unroll
    for (int o = 16; o > 0; o >>= 1) lsum += __shfl_down_sync(0xffffffffu, lsum, o);
    __shared__ double sd[8];
    if ((tid & 31) == 0) sd[tid >> 5] = lsum;
    __syncthreads();
    if (tid == 0) {
        double s = 0.0;
        for (int v = 0; v < 8; v++) s += sd[v];
        atomicAdd(&g_sse, s);
    }
}

// ============================================================
__global__ void vq_finalize_kernel(float* __restrict__ out) {
    __shared__ float red[32];
    int tid = threadIdx.x;
    float p = (float)g_counts[tid] / 65536.0f;
    float t = p * logf(p + 1e-10f);
#pragma unroll
    for (int o = 16; o > 0; o >>= 1) t += __shfl_down_sync(0xffffffffu, t, o);
    if ((tid & 31) == 0) red[tid >> 5] = t;
    __syncthreads();
    if (tid < 32) {
        float v = red[tid];
#pragma unroll
        for (int o = 16; o > 0; o >>= 1) v += __shfl_down_sync(0xffffffffu, v, o);
        if (tid == 0) {
            out[PERP_OFF] = expf(-v);
            float m = (float)(g_sse / 33554432.0);
            out[0] = m + 0.25f * m;
        }
    }
}

// ============================================================
extern "C" void kernel_launch(void* const* d_in, const int* in_sizes, int n_in,
                              void* d_out, int out_size) {
    const float* X = (const float*)d_in[0];
    const float* W = (const float*)d_in[1];
    if (n_in >= 2 && in_sizes[0] == KCODES * DIM && in_sizes[1] == N_ROWS * DIM) {
        const float* t = X; X = W; W = t;
    }
    float* out  = (float*)d_out;
    float* outq = out + QUANT_OFF;
    float* oute = out + ENC_OFF;

    cudaFuncSetAttribute(vq_main,
                         cudaFuncAttributeMaxDynamicSharedMemorySize, SM_TOT);

    vq_prep_all<<<128 + N_ROWS / 8, 256>>>(X, W);
    vq_main<<<N_ROWS / BM, 256, SM_TOT>>>(X, W);
    vq_output_kernel<<<1024, 256>>>(X, W, outq, oute);
    vq_finalize_kernel<<<1, 1024>>>(out);
}

// round 15
// speedup vs baseline: 4.5156x; 1.0488x over previous
#include <cuda_runtime.h>
#include <cstdint>
#include <math.h>

#define N_ROWS 65536
#define DIM    512
#define KCODES 1024

#define QUANT_OFF 1
#define PERP_OFF  (1 + N_ROWS * DIM)
#define ENC_OFF   (2 + (size_t)N_ROWS * DIM)

// CTA = 64 rows x 1024 codes (8 nc x 8 kc chunks); 2 CTAs/SM
#define BM 64
#define BN 128
#define KC 64                  // k per chunk

// smem byte offsets (per CTA)
#define SM_A    0              // 2 x [64 rows][64 k] f32 = 2 x 16384
#define SM_ABUF 16384
#define SM_B    32768          // 2 x [128 codes][64 k] f32 (xor-swizzled) = 2 x 32768
#define SM_BBUF 32768
#define SM_WN   98304          // 128 f32 (reused as double[8] for SSE reduce)
#define SM_XN   98816          // 64 f32
#define SM_BEST 99072          // 64 u64
#define SM_TOT  99584

// ---- scratch ----
__device__ float  g_wnorm[KCODES];
__device__ float  g_xnorm[N_ROWS];
__device__ int    g_idx[N_ROWS];
__device__ int    g_counts[KCODES];
__device__ double g_sse;

// ---- helpers ----
static __device__ __forceinline__ uint64_t cvta_g(const void* p) {
    uint64_t a; asm("cvta.to.global.u64 %0, %1;" : "=l"(a) : "l"(p)); return a;
}
static __device__ __forceinline__ uint32_t smem_u32(const void* p) {
    uint32_t a;
    asm("{ .reg .u64 t; cvta.to.shared.u64 t, %1; cvt.u32.u64 %0, t; }" : "=r"(a) : "l"(p));
    return a;
}
static __device__ __forceinline__ void cp16(uint32_t s, uint64_t g) {
    asm volatile("cp.async.cg.shared.global [%0], [%1], 16;" :: "r"(s), "l"(g));
}
#define CP_COMMIT() asm volatile("cp.async.commit_group;")
#define CP_WAIT(n)  asm volatile("cp.async.wait_group %0;" :: "n"(n))

// packed fp32x2 FMA: lanes accumulate independent (even-k, odd-k) partial dots
static __device__ __forceinline__ void fma2(unsigned long long& c,
                                            unsigned long long a,
                                            unsigned long long b) {
    asm("fma.rn.f32x2 %0, %1, %2, %0;" : "+l"(c) : "l"(a), "l"(b));
}
static __device__ __forceinline__ float unpack_sum(unsigned long long v) {
    float lo, hi;
    asm("mov.b64 {%0,%1}, %2;" : "=f"(lo), "=f"(hi) : "l"(v));
    return lo + hi;
}

// ============================================================
// merged prep: blocks [0,128) -> wnorm (+zero counts/sse),
//              blocks [128,8320) -> xnorm
// ============================================================
__global__ void vq_prep_all(const float* __restrict__ X,
                            const float* __restrict__ W) {
    const int b = blockIdx.x;
    const int w = threadIdx.x >> 5, lane = threadIdx.x & 31;
    if (b < 128) {
        int code = b * 8 + w;
        const float* row = W + (size_t)code * DIM;
        float s = 0.f;
#pragma unroll
        for (int t = 0; t < DIM / 32; t++) { float v = row[lane + t * 32]; s += v * v; }
#pragma unroll
        for (int o = 16; o > 0; o >>= 1) s += __shfl_down_sync(0xffffffffu, s, o);
        if (lane == 0) g_wnorm[code] = s;
        if (b == 0) {
            for (int i = threadIdx.x; i < KCODES; i += blockDim.x) g_counts[i] = 0;
            if (threadIdx.x == 0) g_sse = 0.0;
        }
    } else {
        int r = (b - 128) * 8 + w;
        const float* row = X + (size_t)r * DIM;
        float s = 0.f;
#pragma unroll
        for (int t = 0; t < DIM / 32; t++) { float v = row[lane + t * 32]; s += v * v; }
#pragma unroll
        for (int o = 16; o > 0; o >>= 1) s += __shfl_down_sync(0xffffffffu, s, o);
        if (lane == 0) g_xnorm[r] = s;
    }
}

// ============================================================
// chunk staging
// ============================================================
static __device__ __forceinline__ void stage_a(
    uint32_t sb, const float* __restrict__ X, int r0, int kc, int buf, int tid)
{
    uint64_t xsrc = cvta_g(X) + (size_t)r0 * (DIM * 4) + kc * (KC * 4);
    uint32_t dst = sb + SM_A + buf * SM_ABUF;
#pragma unroll
    for (int i = 0; i < 4; i++) {
        int f = tid + i * 256;          // 0..1023
        int row = f >> 4, k4 = f & 15;
        cp16(dst + row * 256 + k4 * 16,
             xsrc + (size_t)row * (DIM * 4) + k4 * 16);
    }
}
static __device__ __forceinline__ void stage_b(
    uint32_t sb, const float* __restrict__ W, int c0, int kc, int buf, int tid)
{
    uint64_t wsrc = cvta_g(W) + (size_t)c0 * (DIM * 4) + kc * (KC * 4);
    uint32_t dst = sb + SM_B + buf * SM_BBUF;
#pragma unroll
    for (int i = 0; i < 8; i++) {
        int f = tid + i * 256;          // 0..2047
        int code = f >> 4, k4 = f & 15;
        int col = k4 ^ (code & 15);
        cp16(dst + code * 256 + col * 16,
             wsrc + (size_t)code * (DIM * 4) + k4 * 16);
    }
}

// ============================================================
// main: f32x2 exact GEMM + fused argmin + FUSED output tail
// 256 thr = 8(tr) x 32(tc); thread = 8 rows x 4 codes (cols j*32+tc)
// ============================================================
__global__ void __launch_bounds__(256, 2)
vq_main(const float* __restrict__ X, const float* __restrict__ W,
        float* __restrict__ outq, float* __restrict__ oute) {
    extern __shared__ __align__(16) char smem[];
    const uint32_t sb = smem_u32(smem);
    float* sWn = (float*)(smem + SM_WN);
    float* sXn = (float*)(smem + SM_XN);
    unsigned long long* sBest = (unsigned long long*)(smem + SM_BEST);

    const int tid = threadIdx.x;
    const int tr = tid >> 5, tc = tid & 31;
    const int r0 = blockIdx.x * BM;

    // prologue: chunk 0 (A kc=0, B nc=0/kc=0) into buf0
    stage_a(sb, X, r0, 0, 0, tid);
    stage_b(sb, W, 0, 0, 0, tid);
    CP_COMMIT();

    if (tid < BM) {
        sBest[tid] = 0xFFFFFFFFFFFFFFFFull;
        sXn[tid] = g_xnorm[r0 + tid];
    }

    // encodings zero-fill for this CTA's rows (idx-independent; overlaps compute)
    {
        float2 z2 = make_float2(0.f, 0.f);
        for (int f = tid; f < BM * (KCODES / 2); f += 256) {
            int row = f >> 9, q = f & 511;
            ((float2*)(oute + (size_t)(r0 + row) * KCODES))[q] = z2;
        }
    }

    unsigned long long acc[8][4];

    for (int t = 0; t < 64; t++) {
        const int nc = t >> 3, kc = t & 7, buf = t & 1;
        __syncthreads();                 // all warps done reading buf^1 (t-1)
        if (t + 1 < 64) {
            const int nt = t + 1;
            stage_a(sb, X, r0, nt & 7, buf ^ 1, tid);
            stage_b(sb, W, (nt >> 3) * BN, nt & 7, buf ^ 1, tid);
            CP_COMMIT();
            CP_WAIT(1);                  // chunk t landed
        } else {
            CP_WAIT(0);
        }
        __syncthreads();

        if (kc == 0) {
            if (tid < BN) sWn[tid] = g_wnorm[nc * BN + tid];
#pragma unroll
            for (int i = 0; i < 8; i++)
#pragma unroll
                for (int j = 0; j < 4; j++) acc[i][j] = 0ull;
        }

        const char* pB = smem + SM_B + buf * SM_BBUF;
        const float* pA = (const float*)(smem + SM_A + buf * SM_ABUF)
                          + (tr * 8) * KC;
#pragma unroll
        for (int k4 = 0; k4 < 16; k4++) {
            const int col16 = (k4 ^ (tc & 15)) << 4;
            ulonglong2 bv[4];
#pragma unroll
            for (int j = 0; j < 4; j++)
                bv[j] = *(const ulonglong2*)(pB + (j * 32 + tc) * 256 + col16);
#pragma unroll
            for (int i = 0; i < 8; i++) {
                ulonglong2 av = *(const ulonglong2*)(pA + i * KC + k4 * 4);
#pragma unroll
                for (int j = 0; j < 4; j++)
                    fma2(acc[i][j], av.x, bv[j].x);
#pragma unroll
                for (int j = 0; j < 4; j++)
                    fma2(acc[i][j], av.y, bv[j].y);
            }
        }

        if (kc == 7) {
            // ---- epilogue: distances + per-row argmin (first-index ties) ----
            const int c0 = nc * BN;
#pragma unroll
            for (int i = 0; i < 8; i++) {
                int row = tr * 8 + i;
                float xn = sXn[row];
                unsigned long long best = 0xFFFFFFFFFFFFFFFFull;
#pragma unroll
                for (int j = 0; j < 4; j++) {
                    int col = j * 32 + tc;
                    float dot = unpack_sum(acc[i][j]);
                    float d = (xn + sWn[col]) - 2.0f * dot;   // reference formula
                    unsigned key = __float_as_uint(d);
                    key = (key & 0x80000000u) ? ~key : (key | 0x80000000u);
                    unsigned long long pk =
                        ((unsigned long long)key << 32) | (unsigned)(c0 + col);
                    if (pk < best) best = pk;
                }
                atomicMin(&sBest[row], best);
            }
        }
    }

    __syncthreads();                     // argmins final; zero-fill ordered before
    if (tid < BM) {
        int idx = (int)(sBest[tid] & 0xFFFFFFFFu);
        g_idx[r0 + tid] = idx;
        atomicAdd(&g_counts[idx], 1);
        oute[(size_t)(r0 + tid) * KCODES + idx] = 1.0f;   // one-hot scatter
    }

    // ---- fused output tail: quantized_st + SSE (rows r0..r0+63) ----
    {
        const int sub = tid >> 7, c4 = tid & 127;
        float a0 = 0.f, a1 = 0.f, a2 = 0.f, a3 = 0.f;
#pragma unroll 4
        for (int i = 0; i < 32; i++) {
            int rl = i * 2 + sub;
            int r = r0 + rl;
            int idx = (int)(sBest[rl] & 0xFFFFFFFFu);
            float4 xv = ((const float4*)(X + (size_t)r * DIM))[c4];
            float4 qv = ((const float4*)(W + (size_t)idx * DIM))[c4];
            float dx = qv.x - xv.x, dy = qv.y - xv.y;
            float dz = qv.z - xv.z, dw = qv.w - xv.w;
            float* op = outq + (size_t)r * DIM + c4 * 4;   // 4B-aligned: scalar STG
            op[0] = xv.x + dx; op[1] = xv.y + dy;
            op[2] = xv.z + dz; op[3] = xv.w + dw;
            a0 += dx * dx; a1 += dy * dy; a2 += dz * dz; a3 += dw * dw;
        }
        double lsum = (double)((a0 + a1) + (a2 + a3));
#pragma unroll
        for (int o = 16; o > 0; o >>= 1)
            lsum += __shfl_down_sync(0xffffffffu, lsum, o);
        double* sd = (double*)(smem + SM_WN);   // sWn dead after last epilogue
        __syncthreads();
        if ((tid & 31) == 0) sd[tid >> 5] = lsum;
        __syncthreads();
        if (tid == 0) {
            double s = 0.0;
            for (int v = 0; v < 8; v++) s += sd[v];
            atomicAdd(&g_sse, s);
        }
    }
}

// ============================================================
__global__ void vq_finalize_kernel(float* __restrict__ out) {
    __shared__ float red[32];
    int tid = threadIdx.x;
    float p = (float)g_counts[tid] / 65536.0f;
    float t = p * logf(p + 1e-10f);
#pragma unroll
    for (int o = 16; o > 0; o >>= 1) t += __shfl_down_sync(0xffffffffu, t, o);
    if ((tid & 31) == 0) red[tid >> 5] = t;
    __syncthreads();
    if (tid < 32) {
        float v = red[tid];
#pragma unroll
        for (int o = 16; o > 0; o >>= 1) v += __shfl_down_sync(0xffffffffu, v, o);
        if (tid == 0) {
            out[PERP_OFF] = expf(-v);
            float m = (float)(g_sse / 33554432.0);
            out[0] = m + 0.25f * m;
        }
    }
}

// ============================================================
extern "C" void kernel_launch(void* const* d_in, const int* in_sizes, int n_in,
                              void* d_out, int out_size) {
    const float* X = (const float*)d_in[0];
    const float* W = (const float*)d_in[1];
    if (n_in >= 2 && in_sizes[0] == KCODES * DIM && in_sizes[1] == N_ROWS * DIM) {
        const float* t = X; X = W; W = t;
    }
    float* out  = (float*)d_out;
    float* outq = out + QUANT_OFF;
    float* oute = out + ENC_OFF;

    cudaFuncSetAttribute(vq_main,
                         cudaFuncAttributeMaxDynamicSharedMemorySize, SM_TOT);

    vq_prep_all<<<128 + N_ROWS / 8, 256>>>(X, W);
    vq_main<<<N_ROWS / BM, 256, SM_TOT>>>(X, W, outq, oute);
    vq_finalize_kernel<<<1, 1024>>>(out);
}

// round 16
// speedup vs baseline: 4.5416x; 1.0057x over previous
#include <cuda_runtime.h>
#include <cstdint>
#include <math.h>

#define N_ROWS 65536
#define DIM    512
#define KCODES 1024

#define QUANT_OFF 1
#define PERP_OFF  (1 + N_ROWS * DIM)
#define ENC_OFF   (2 + (size_t)N_ROWS * DIM)

// CTA = 64 rows x 1024 codes (8 nc x 8 kc chunks); 2 CTAs/SM
#define BM 64
#define BN 128
#define KC 64                  // k per chunk
#define NCTAS (N_ROWS / BM)    // 1024

// smem byte offsets (per CTA)
#define SM_A    0              // 2 x [64 rows][64 k] f32 = 2 x 16384
#define SM_ABUF 16384
#define SM_B    32768          // 2 x [128 codes][64 k] f32 (xor-swizzled) = 2 x 32768
#define SM_BBUF 32768
#define SM_WN   98304          // 128 f32 (reused as double[8] + flag late)
#define SM_XN   98816          // 64 f32
#define SM_BEST 99072          // 64 u64
#define SM_PART 99584          // 256 f32 xnorm partials
#define SM_TOT  100608

// ---- scratch ----
__device__ float  g_wnorm[KCODES];
__device__ int    g_counts[KCODES];
__device__ double g_sse;
__device__ int    g_done;

// ---- helpers ----
static __device__ __forceinline__ uint64_t cvta_g(const void* p) {
    uint64_t a; asm("cvta.to.global.u64 %0, %1;" : "=l"(a) : "l"(p)); return a;
}
static __device__ __forceinline__ uint32_t smem_u32(const void* p) {
    uint32_t a;
    asm("{ .reg .u64 t; cvta.to.shared.u64 t, %1; cvt.u32.u64 %0, t; }" : "=r"(a) : "l"(p));
    return a;
}
static __device__ __forceinline__ void cp16(uint32_t s, uint64_t g) {
    asm volatile("cp.async.cg.shared.global [%0], [%1], 16;" :: "r"(s), "l"(g));
}
#define CP_COMMIT() asm volatile("cp.async.commit_group;")
#define CP_WAIT(n)  asm volatile("cp.async.wait_group %0;" :: "n"(n))

// packed fp32x2 FMA: lanes accumulate independent (even-k, odd-k) partial dots
static __device__ __forceinline__ void fma2(unsigned long long& c,
                                            unsigned long long a,
                                            unsigned long long b) {
    asm("fma.rn.f32x2 %0, %1, %2, %0;" : "+l"(c) : "l"(a), "l"(b));
}
static __device__ __forceinline__ float unpack_sum(unsigned long long v) {
    float lo, hi;
    asm("mov.b64 {%0,%1}, %2;" : "=f"(lo), "=f"(hi) : "l"(v));
    return lo + hi;
}

// ============================================================
// prep: wnorm per code + zero counts/sse  (W only: ~2MB read)
// ============================================================
__global__ void vq_prep_kernel(const float* __restrict__ W) {
    int w = threadIdx.x >> 5, lane = threadIdx.x & 31;
    int code = blockIdx.x * 8 + w;
    const float* row = W + (size_t)code * DIM;
    float s = 0.f;
#pragma unroll
    for (int t = 0; t < DIM / 32; t++) { float v = row[lane + t * 32]; s += v * v; }
#pragma unroll
    for (int o = 16; o > 0; o >>= 1) s += __shfl_down_sync(0xffffffffu, s, o);
    if (lane == 0) g_wnorm[code] = s;
    if (blockIdx.x == 0) {
        for (int i = threadIdx.x; i < KCODES; i += blockDim.x) g_counts[i] = 0;
        if (threadIdx.x == 0) g_sse = 0.0;
    }
}

// ============================================================
// chunk staging
// ============================================================
static __device__ __forceinline__ void stage_a(
    uint32_t sb, const float* __restrict__ X, int r0, int kc, int buf, int tid)
{
    uint64_t xsrc = cvta_g(X) + (size_t)r0 * (DIM * 4) + kc * (KC * 4);
    uint32_t dst = sb + SM_A + buf * SM_ABUF;
#pragma unroll
    for (int i = 0; i < 4; i++) {
        int f = tid + i * 256;          // 0..1023
        int row = f >> 4, k4 = f & 15;
        cp16(dst + row * 256 + k4 * 16,
             xsrc + (size_t)row * (DIM * 4) + k4 * 16);
    }
}
static __device__ __forceinline__ void stage_b(
    uint32_t sb, const float* __restrict__ W, int c0, int kc, int buf, int tid)
{
    uint64_t wsrc = cvta_g(W) + (size_t)c0 * (DIM * 4) + kc * (KC * 4);
    uint32_t dst = sb + SM_B + buf * SM_BBUF;
#pragma unroll
    for (int i = 0; i < 8; i++) {
        int f = tid + i * 256;          // 0..2047
        int code = f >> 4, k4 = f & 15;
        int col = k4 ^ (code & 15);
        cp16(dst + code * 256 + col * 16,
             wsrc + (size_t)code * (DIM * 4) + k4 * 16);
    }
}

// ============================================================
// main: f32x2 exact GEMM + fused argmin + fused output + fused finalize
// 256 thr = 8(tr) x 32(tc); thread = 8 rows x 4 codes (cols j*32+tc)
// ============================================================
__global__ void __launch_bounds__(256, 2)
vq_main(const float* __restrict__ X, const float* __restrict__ W,
        float* __restrict__ out, float* __restrict__ outq,
        float* __restrict__ oute) {
    extern __shared__ __align__(16) char smem[];
    const uint32_t sb = smem_u32(smem);
    float* sWn = (float*)(smem + SM_WN);
    float* sXn = (float*)(smem + SM_XN);
    unsigned long long* sBest = (unsigned long long*)(smem + SM_BEST);
    float* sPart = (float*)(smem + SM_PART);

    const int tid = threadIdx.x;
    const int tr = tid >> 5, tc = tid & 31;
    const int r0 = blockIdx.x * BM;

    // prologue: chunk 0 (A kc=0, B nc=0/kc=0) into buf0
    stage_a(sb, X, r0, 0, 0, tid);
    stage_b(sb, W, 0, 0, 0, tid);
    CP_COMMIT();

    if (tid < BM) sBest[tid] = 0xFFFFFFFFFFFFFFFFull;

    // encodings zero-fill for this CTA's rows (idx-independent; overlaps compute)
    {
        float2 z2 = make_float2(0.f, 0.f);
        for (int f = tid; f < BM * (KCODES / 2); f += 256) {
            int row = f >> 9, q = f & 511;
            ((float2*)(oute + (size_t)(r0 + row) * KCODES))[q] = z2;
        }
    }

    unsigned long long acc[8][4];
    float xpart = 0.f;                   // xnorm partial (row tid>>2, part tid&3)

    for (int t = 0; t < 64; t++) {
        const int nc = t >> 3, kc = t & 7, buf = t & 1;
        __syncthreads();                 // all warps done reading buf^1 (t-1)
        if (t + 1 < 64) {
            const int nt = t + 1;
            stage_a(sb, X, r0, nt & 7, buf ^ 1, tid);
            stage_b(sb, W, (nt >> 3) * BN, nt & 7, buf ^ 1, tid);
            CP_COMMIT();
            CP_WAIT(1);                  // chunk t landed
        } else {
            CP_WAIT(0);
        }
        __syncthreads();

        if (t < 8) {                     // nc==0: accumulate xnorm from A chunks
            const float* ax = (const float*)(smem + SM_A + buf * SM_ABUF)
                              + (tid >> 2) * KC + (tid & 3) * 16;
#pragma unroll
            for (int q = 0; q < 16; q++) { float v = ax[q]; xpart += v * v; }
            if (t == 7) {                // full k covered: reduce to sXn
                sPart[tid] = xpart;
                __syncthreads();
                if (tid < BM) {
                    float* p = sPart + tid * 4;
                    sXn[tid] = (p[0] + p[1]) + (p[2] + p[3]);
                }
                __syncthreads();
            }
        }

        if (kc == 0) {
            if (tid < BN) sWn[tid] = g_wnorm[nc * BN + tid];
#pragma unroll
            for (int i = 0; i < 8; i++)
#pragma unroll
                for (int j = 0; j < 4; j++) acc[i][j] = 0ull;
        }

        const char* pB = smem + SM_B + buf * SM_BBUF;
        const float* pA = (const float*)(smem + SM_A + buf * SM_ABUF)
                          + (tr * 8) * KC;
#pragma unroll
        for (int k4 = 0; k4 < 16; k4++) {
            const int col16 = (k4 ^ (tc & 15)) << 4;
            ulonglong2 bv[4];
#pragma unroll
            for (int j = 0; j < 4; j++)
                bv[j] = *(const ulonglong2*)(pB + (j * 32 + tc) * 256 + col16);
#pragma unroll
            for (int i = 0; i < 8; i++) {
                ulonglong2 av = *(const ulonglong2*)(pA + i * KC + k4 * 4);
#pragma unroll
                for (int j = 0; j < 4; j++)
                    fma2(acc[i][j], av.x, bv[j].x);
#pragma unroll
                for (int j = 0; j < 4; j++)
                    fma2(acc[i][j], av.y, bv[j].y);
            }
        }

        if (kc == 7) {
            // ---- epilogue: distances + per-row argmin (first-index ties) ----
            const int c0 = nc * BN;
#pragma unroll
            for (int i = 0; i < 8; i++) {
                int row = tr * 8 + i;
                float xn = sXn[row];
                unsigned long long best = 0xFFFFFFFFFFFFFFFFull;
#pragma unroll
                for (int j = 0; j < 4; j++) {
                    int col = j * 32 + tc;
                    float dot = unpack_sum(acc[i][j]);
                    float d = (xn + sWn[col]) - 2.0f * dot;   // reference formula
                    unsigned key = __float_as_uint(d);
                    key = (key & 0x80000000u) ? ~key : (key | 0x80000000u);
                    unsigned long long pk =
                        ((unsigned long long)key << 32) | (unsigned)(c0 + col);
                    if (pk < best) best = pk;
                }
                atomicMin(&sBest[row], best);
            }
        }
    }

    __syncthreads();                     // argmins final; zero-fill ordered before
    if (tid < BM) {
        int idx = (int)(sBest[tid] & 0xFFFFFFFFu);
        atomicAdd(&g_counts[idx], 1);
        oute[(size_t)(r0 + tid) * KCODES + idx] = 1.0f;   // one-hot scatter
    }

    // ---- fused output tail: quantized_st + SSE (rows r0..r0+63) ----
    {
        const int sub = tid >> 7, c4 = tid & 127;
        float a0 = 0.f, a1 = 0.f, a2 = 0.f, a3 = 0.f;
#pragma unroll 4
        for (int i = 0; i < 32; i++) {
            int rl = i * 2 + sub;
            int r = r0 + rl;
            int idx = (int)(sBest[rl] & 0xFFFFFFFFu);
            float4 xv = ((const float4*)(X + (size_t)r * DIM))[c4];
            float4 qv = ((const float4*)(W + (size_t)idx * DIM))[c4];
            float dx = qv.x - xv.x, dy = qv.y - xv.y;
            float dz = qv.z - xv.z, dw = qv.w - xv.w;
            float* op = outq + (size_t)r * DIM + c4 * 4;   // 4B-aligned: scalar STG
            op[0] = xv.x + dx; op[1] = xv.y + dy;
            op[2] = xv.z + dz; op[3] = xv.w + dw;
            a0 += dx * dx; a1 += dy * dy; a2 += dz * dz; a3 += dw * dw;
        }
        double lsum = (double)((a0 + a1) + (a2 + a3));
#pragma unroll
        for (int o = 16; o > 0; o >>= 1)
            lsum += __shfl_down_sync(0xffffffffu, lsum, o);
        double* sd = (double*)(smem + SM_WN);   // sWn dead after last epilogue
        __syncthreads();
        if ((tid & 31) == 0) sd[tid >> 5] = lsum;
        __syncthreads();
        if (tid == 0) {
            double s = 0.0;
            for (int v = 0; v < 8; v++) s += sd[v];
            atomicAdd(&g_sse, s);
        }
    }

    // ---- fused finalize: last CTA computes loss + perplexity ----
    int* sFlag = (int*)(smem + SM_PART);
    if (tid == 0) {
        __threadfence();
        sFlag[0] = (atomicAdd(&g_done, 1) == NCTAS - 1) ? 1 : 0;
    }
    __syncthreads();
    if (sFlag[0]) {
        float tacc = 0.f;
#pragma unroll
        for (int q = 0; q < 4; q++) {
            int c = tid + q * 256;
            float p = (float)(*(volatile int*)&g_counts[c]) / 65536.0f;
            tacc += p * logf(p + 1e-10f);
        }
#pragma unroll
        for (int o = 16; o > 0; o >>= 1)
            tacc += __shfl_down_sync(0xffffffffu, tacc, o);
        float* red = (float*)(smem + SM_XN);
        if ((tid & 31) == 0) red[tid >> 5] = tacc;
        __syncthreads();
        if (tid == 0) {
            float v = 0.f;
            for (int w = 0; w < 8; w++) v += red[w];
            out[PERP_OFF] = expf(-v);
            double sse = *(volatile double*)&g_sse;
            float m = (float)(sse / 33554432.0);
            out[0] = m + 0.25f * m;
            g_done = 0;                  // reset for next graph replay
        }
    }
}

// ============================================================
extern "C" void kernel_launch(void* const* d_in, const int* in_sizes, int n_in,
                              void* d_out, int out_size) {
    const float* X = (const float*)d_in[0];
    const float* W = (const float*)d_in[1];
    if (n_in >= 2 && in_sizes[0] == KCODES * DIM && in_sizes[1] == N_ROWS * DIM) {
        const float* t = X; X = W; W = t;
    }
    float* out  = (float*)d_out;
    float* outq = out + QUANT_OFF;
    float* oute = out + ENC_OFF;

    cudaFuncSetAttribute(vq_main,
                         cudaFuncAttributeMaxDynamicSharedMemorySize, SM_TOT);

    vq_prep_kernel<<<128, 256>>>(W);
    vq_main<<<NCTAS, 256, SM_TOT>>>(X, W, out, outq, oute);
}